// round 6
// baseline (speedup 1.0000x reference)
#include <cuda_runtime.h>
#include <cstdint>

// Problem constants (fixed by the dataset instance).
#define BB 512
#define LL 512
#define CC 256
#define C4 64                 // float4 per channel row
#define NTH 256
#define LGR 4                 // l-groups (tid >> 6)
#define GRID 256
#define TPB 2                 // full batches per block

// Least-squares constants for t = 0..511:
//   sum_t = 130816, sum_t2 = 44608256, denom = sum_t2 - sum_t^2/n = 11184768
#define SUM_T     130816.0f
#define K1        255.5f
#define INV_DENOM (1.0f / 11184768.0f)
#define INV_N     (1.0f / 512.0f)

__device__ __forceinline__ void f4add(float4& a, const float4 b) {
    a.x += b.x; a.y += b.y; a.z += b.z; a.w += b.w;
}

__global__ __launch_bounds__(NTH)
void lr_forecast_skew2(const float* __restrict__ x,
                       float* __restrict__ out,
                       int t_out_len)
{
    const int g   = blockIdx.x;
    const int tid = threadIdx.x;
    const int c4  = tid & (C4 - 1);   // 0..63 (float4 column)
    const int lg  = tid >> 6;          // 0..3  (l-stride group)

    __shared__ float4 s_sy [LGR][C4];
    __shared__ float4 s_sty[LGR][C4];
    __shared__ float4 s_sl[C4];
    __shared__ float4 s_ic[C4];

    // ---- monolithic read phase: one contiguous 512 KB stream per batch ----
    auto read_tile = [&](int b, float4& sl_o, float4& ic_o) {
        const float4* xb = reinterpret_cast<const float4*>(
                               x + (size_t)b * LL * CC) + c4;
        float4 sy  = make_float4(0.f, 0.f, 0.f, 0.f);
        float4 sty = make_float4(0.f, 0.f, 0.f, 0.f);
        #pragma unroll 8
        for (int l = lg; l < LL; l += LGR) {      // 128 iters / thread
            float4 v = __ldg(&xb[(size_t)l * C4]);
            float tf = (float)l;
            f4add(sy, v);
            sty.x = fmaf(tf, v.x, sty.x);
            sty.y = fmaf(tf, v.y, sty.y);
            sty.z = fmaf(tf, v.z, sty.z);
            sty.w = fmaf(tf, v.w, sty.w);
        }
        s_sy [lg][c4] = sy;
        s_sty[lg][c4] = sty;
        __syncthreads();
        if (lg == 0) {
            float4 Sy = s_sy[0][c4], Sty = s_sty[0][c4];
            #pragma unroll
            for (int k = 1; k < LGR; k++) {
                f4add(Sy,  s_sy [k][c4]);
                f4add(Sty, s_sty[k][c4]);
            }
            float4 SL, IC;
            SL.x = (Sty.x - K1 * Sy.x) * INV_DENOM;
            SL.y = (Sty.y - K1 * Sy.y) * INV_DENOM;
            SL.z = (Sty.z - K1 * Sy.z) * INV_DENOM;
            SL.w = (Sty.w - K1 * Sy.w) * INV_DENOM;
            IC.x = (Sy.x - SL.x * SUM_T) * INV_N;
            IC.y = (Sy.y - SL.y * SUM_T) * INV_N;
            IC.z = (Sy.z - SL.z * SUM_T) * INV_N;
            IC.w = (Sy.w - SL.w * SUM_T) * INV_N;
            s_sl[c4] = SL;
            s_ic[c4] = IC;
        }
        __syncthreads();
        sl_o = s_sl[c4];
        ic_o = s_ic[c4];
        __syncthreads();   // smem reused by the next read_tile
    };

    // ---- monolithic write phase: one contiguous 623 KB stream per batch ----
    auto write_tile = [&](int b, float4 sl, float4 ic) {
        float4* ob = reinterpret_cast<float4*>(
                         out + (size_t)b * t_out_len * CC) + c4;
        #pragma unroll 8
        for (int t = lg; t < t_out_len; t += LGR) {   // 152 iters / thread
            float tf = (float)t;
            float4 o;
            o.x = fmaf(sl.x, tf, ic.x);
            o.y = fmaf(sl.y, tf, ic.y);
            o.z = fmaf(sl.z, tf, ic.z);
            o.w = fmaf(sl.w, tf, ic.w);
            ob[(size_t)t * C4] = o;
        }
    };

    float4 sl0, ic0, sl1, ic1;

    if ((g & 1) == 0) {
        // Even blocks: R0 W0 R1 W1
        #pragma unroll
        for (int s = 0; s < TPB; s++) {
            int b = g + s * GRID;
            read_tile(b, sl0, ic0);
            write_tile(b, sl0, ic0);
        }
    } else {
        // Odd blocks: R0 R1 W0 W1  (writes overlap even blocks' reads and v.v.)
        read_tile(g, sl0, ic0);
        read_tile(g + GRID, sl1, ic1);
        write_tile(g, sl0, ic0);
        write_tile(g + GRID, sl1, ic1);
    }
}

extern "C" void kernel_launch(void* const* d_in, const int* in_sizes, int n_in,
                              void* d_out, int out_size)
{
    const float* x = (const float*)d_in[0];
    float* out = (float*)d_out;
    int t_out_len = out_size / (BB * CC);   // 608 for pred_len = 96

    lr_forecast_skew2<<<GRID, NTH>>>(x, out, t_out_len);
}

// round 7
// speedup vs baseline: 1.0996x; 1.0996x over previous
#include <cuda_runtime.h>
#include <cstdint>

// Problem constants (fixed by the dataset instance).
#define BB 512
#define LL 512
#define CC 256
#define NTH 256
#define CSL 4                 // channel slices per batch (64 ch = 16 float4 each)
#define C4S 16                // float4 per slice
#define LGR 16                // l-groups (tid >> 4)
#define RITER (LL / LGR)      // 32 read iters per tile
#define TILES (BB * CSL)      // 2048
#define GRID 1024
#define TPB (TILES / GRID)    // 2 tiles per block
#define C4FULL (CC / 4)       // 64 float4 per full row

// Least-squares constants for t = 0..511:
//   sum_t = 130816, sum_t2 = 44608256, denom = sum_t2 - sum_t^2/n = 11184768
#define SUM_T     130816.0f
#define K1        255.5f
#define INV_DENOM (1.0f / 11184768.0f)
#define INV_N     (1.0f / 512.0f)

__device__ __forceinline__ void f4add(float4& a, const float4 b) {
    a.x += b.x; a.y += b.y; a.z += b.z; a.w += b.w;
}

__global__ __launch_bounds__(NTH)
void lr_forecast_skew3(const float* __restrict__ x,
                       float* __restrict__ out,
                       int t_out_len)
{
    const int g   = blockIdx.x;
    const int tid = threadIdx.x;
    const int c4  = tid & (C4S - 1);   // 0..15
    const int lg  = tid >> 4;          // 0..15

    __shared__ float4 s_sy [LGR][C4S];
    __shared__ float4 s_sty[LGR][C4S];
    __shared__ float4 s_sl[C4S];
    __shared__ float4 s_ic[C4S];

    // ---- monolithic read phase (front-batched 8-deep LDG.128) ----
    auto read_tile = [&](int tile, float4& sl_o, float4& ic_o) {
        const int b  = tile >> 2;
        const int cs = tile & (CSL - 1);
        const float4* xb = reinterpret_cast<const float4*>(
                               x + (size_t)b * LL * CC) + cs * C4S + c4;
        float4 sy  = make_float4(0.f, 0.f, 0.f, 0.f);
        float4 sty = make_float4(0.f, 0.f, 0.f, 0.f);
        #pragma unroll 8
        for (int i = 0; i < RITER; i++) {
            int l = lg + i * LGR;
            float4 v = __ldg(&xb[(size_t)l * C4FULL]);
            float tf = (float)l;
            f4add(sy, v);
            sty.x = fmaf(tf, v.x, sty.x);
            sty.y = fmaf(tf, v.y, sty.y);
            sty.z = fmaf(tf, v.z, sty.z);
            sty.w = fmaf(tf, v.w, sty.w);
        }
        // reduce 16 l-groups
        s_sy [lg][c4] = sy;
        s_sty[lg][c4] = sty;
        __syncthreads();
        if (lg < 4) {
            float4 a = s_sy[lg][c4];
            f4add(a, s_sy[lg +  4][c4]);
            f4add(a, s_sy[lg +  8][c4]);
            f4add(a, s_sy[lg + 12][c4]);
            s_sy[lg][c4] = a;
            float4 t = s_sty[lg][c4];
            f4add(t, s_sty[lg +  4][c4]);
            f4add(t, s_sty[lg +  8][c4]);
            f4add(t, s_sty[lg + 12][c4]);
            s_sty[lg][c4] = t;
        }
        __syncthreads();
        if (lg == 0) {
            float4 Sy = s_sy[0][c4], Sty = s_sty[0][c4];
            f4add(Sy,  s_sy [1][c4]); f4add(Sy,  s_sy [2][c4]); f4add(Sy,  s_sy [3][c4]);
            f4add(Sty, s_sty[1][c4]); f4add(Sty, s_sty[2][c4]); f4add(Sty, s_sty[3][c4]);
            float4 SL, IC;
            SL.x = (Sty.x - K1 * Sy.x) * INV_DENOM;
            SL.y = (Sty.y - K1 * Sy.y) * INV_DENOM;
            SL.z = (Sty.z - K1 * Sy.z) * INV_DENOM;
            SL.w = (Sty.w - K1 * Sy.w) * INV_DENOM;
            IC.x = (Sy.x - SL.x * SUM_T) * INV_N;
            IC.y = (Sy.y - SL.y * SUM_T) * INV_N;
            IC.z = (Sy.z - SL.z * SUM_T) * INV_N;
            IC.w = (Sy.w - SL.w * SUM_T) * INV_N;
            s_sl[c4] = SL;
            s_ic[c4] = IC;
        }
        __syncthreads();
        sl_o = s_sl[c4];
        ic_o = s_ic[c4];
        __syncthreads();   // protect smem for the next read_tile
    };

    // ---- monolithic write phase ----
    auto write_tile = [&](int tile, float4 sl, float4 ic) {
        const int b  = tile >> 2;
        const int cs = tile & (CSL - 1);
        float4* ob = reinterpret_cast<float4*>(
                         out + (size_t)b * t_out_len * CC) + cs * C4S + c4;
        #pragma unroll 8
        for (int t = lg; t < t_out_len; t += LGR) {
            float tf = (float)t;
            float4 o;
            o.x = fmaf(sl.x, tf, ic.x);
            o.y = fmaf(sl.y, tf, ic.y);
            o.z = fmaf(sl.z, tf, ic.z);
            o.w = fmaf(sl.w, tf, ic.w);
            ob[(size_t)t * C4FULL] = o;
        }
    };

    float4 sl0, ic0, sl1, ic1;

    if ((g & 1) == 0) {
        // Even blocks: R0 W0 R1 W1
        #pragma unroll
        for (int s = 0; s < TPB; s++) {
            int tile = g + s * GRID;
            read_tile(tile, sl0, ic0);
            write_tile(tile, sl0, ic0);
        }
    } else {
        // Odd blocks: R0 R1 W0 W1 (their writes overlap even blocks' reads)
        read_tile(g, sl0, ic0);
        read_tile(g + GRID, sl1, ic1);
        write_tile(g, sl0, ic0);
        write_tile(g + GRID, sl1, ic1);
    }
}

extern "C" void kernel_launch(void* const* d_in, const int* in_sizes, int n_in,
                              void* d_out, int out_size)
{
    const float* x = (const float*)d_in[0];
    float* out = (float*)d_out;
    int t_out_len = out_size / (BB * CC);   // 608 for pred_len = 96

    lr_forecast_skew3<<<GRID, NTH>>>(x, out, t_out_len);
}

// round 8
// speedup vs baseline: 1.1380x; 1.0349x over previous
#include <cuda_runtime.h>
#include <cstdint>

// Problem constants (fixed by the dataset instance).
#define BB 512
#define LL 512
#define CC 256
#define NTH 256
#define CSL 8                 // channel slices per batch (32 ch = 8 float4 each)
#define C4S 8                 // float4 per slice
#define LGR 32                // l-groups (tid >> 3)
#define RITER (LL / LGR)      // 16 read iters per tile
#define TILES (BB * CSL)      // 4096
#define GRID 1024
#define TPB (TILES / GRID)    // 4 tiles per block
#define C4FULL (CC / 4)       // 64 float4 per full row

// Least-squares constants for t = 0..511:
//   sum_t = 130816, sum_t2 = 44608256, denom = sum_t2 - sum_t^2/n = 11184768
#define SUM_T     130816.0f
#define K1        255.5f
#define INV_DENOM (1.0f / 11184768.0f)
#define INV_N     (1.0f / 512.0f)

__device__ __forceinline__ void f4add(float4& a, const float4 b) {
    a.x += b.x; a.y += b.y; a.z += b.z; a.w += b.w;
}

__global__ __launch_bounds__(NTH)
void lr_forecast_skew4(const float* __restrict__ x,
                       float* __restrict__ out,
                       int t_out_len)
{
    const int g   = blockIdx.x;
    const int tid = threadIdx.x;
    const int c4  = tid & (C4S - 1);   // 0..7
    const int lg  = tid >> 3;          // 0..31

    __shared__ float4 s_sy [LGR][C4S];
    __shared__ float4 s_sty[LGR][C4S];
    __shared__ float4 s_sl[C4S];
    __shared__ float4 s_ic[C4S];

    // ---- monolithic read phase (front-batched 8-deep LDG.128) ----
    auto read_tile = [&](int tile, float4& sl_o, float4& ic_o) {
        const int b  = tile >> 3;
        const int cs = tile & (CSL - 1);
        const float4* xb = reinterpret_cast<const float4*>(
                               x + (size_t)b * LL * CC) + cs * C4S + c4;
        float4 sy  = make_float4(0.f, 0.f, 0.f, 0.f);
        float4 sty = make_float4(0.f, 0.f, 0.f, 0.f);
        #pragma unroll 8
        for (int i = 0; i < RITER; i++) {
            int l = lg + i * LGR;
            float4 v = __ldg(&xb[(size_t)l * C4FULL]);
            float tf = (float)l;
            f4add(sy, v);
            sty.x = fmaf(tf, v.x, sty.x);
            sty.y = fmaf(tf, v.y, sty.y);
            sty.z = fmaf(tf, v.z, sty.z);
            sty.w = fmaf(tf, v.w, sty.w);
        }
        // reduce 32 l-groups: 32 -> 8 -> 1
        s_sy [lg][c4] = sy;
        s_sty[lg][c4] = sty;
        __syncthreads();
        if (lg < 8) {
            float4 a = s_sy[lg][c4];
            f4add(a, s_sy[lg +  8][c4]);
            f4add(a, s_sy[lg + 16][c4]);
            f4add(a, s_sy[lg + 24][c4]);
            s_sy[lg][c4] = a;
            float4 t = s_sty[lg][c4];
            f4add(t, s_sty[lg +  8][c4]);
            f4add(t, s_sty[lg + 16][c4]);
            f4add(t, s_sty[lg + 24][c4]);
            s_sty[lg][c4] = t;
        }
        __syncthreads();
        if (lg == 0) {
            float4 Sy = s_sy[0][c4], Sty = s_sty[0][c4];
            #pragma unroll
            for (int k = 1; k < 8; k++) {
                f4add(Sy,  s_sy [k][c4]);
                f4add(Sty, s_sty[k][c4]);
            }
            float4 SL, IC;
            SL.x = (Sty.x - K1 * Sy.x) * INV_DENOM;
            SL.y = (Sty.y - K1 * Sy.y) * INV_DENOM;
            SL.z = (Sty.z - K1 * Sy.z) * INV_DENOM;
            SL.w = (Sty.w - K1 * Sy.w) * INV_DENOM;
            IC.x = (Sy.x - SL.x * SUM_T) * INV_N;
            IC.y = (Sy.y - SL.y * SUM_T) * INV_N;
            IC.z = (Sy.z - SL.z * SUM_T) * INV_N;
            IC.w = (Sy.w - SL.w * SUM_T) * INV_N;
            s_sl[c4] = SL;
            s_ic[c4] = IC;
        }
        __syncthreads();
        sl_o = s_sl[c4];
        ic_o = s_ic[c4];
        __syncthreads();   // protect smem for the next read_tile
    };

    // ---- monolithic write phase ----
    auto write_tile = [&](int tile, float4 sl, float4 ic) {
        const int b  = tile >> 3;
        const int cs = tile & (CSL - 1);
        float4* ob = reinterpret_cast<float4*>(
                         out + (size_t)b * t_out_len * CC) + cs * C4S + c4;
        #pragma unroll 8
        for (int t = lg; t < t_out_len; t += LGR) {   // 19 iters
            float tf = (float)t;
            float4 o;
            o.x = fmaf(sl.x, tf, ic.x);
            o.y = fmaf(sl.y, tf, ic.y);
            o.z = fmaf(sl.z, tf, ic.z);
            o.w = fmaf(sl.w, tf, ic.w);
            ob[(size_t)t * C4FULL] = o;
        }
    };

    float4 sl0, ic0, sl1, ic1;

    if ((g & 1) == 0) {
        // Even blocks: R0 W0 R1 W1 R2 W2 R3 W3
        #pragma unroll
        for (int s = 0; s < TPB; s++) {
            int tile = g + s * GRID;
            read_tile(tile, sl0, ic0);
            write_tile(tile, sl0, ic0);
        }
    } else {
        // Odd blocks (depth-2 pipeline): R0 R1 W0 R2 W1 R3 W2 W3
        read_tile(g, sl0, ic0);
        #pragma unroll
        for (int s = 1; s < TPB; s++) {
            read_tile(g + s * GRID, sl1, ic1);
            write_tile(g + (s - 1) * GRID, sl0, ic0);
            sl0 = sl1; ic0 = ic1;
        }
        write_tile(g + (TPB - 1) * GRID, sl0, ic0);
    }
}

extern "C" void kernel_launch(void* const* d_in, const int* in_sizes, int n_in,
                              void* d_out, int out_size)
{
    const float* x = (const float*)d_in[0];
    float* out = (float*)d_out;
    int t_out_len = out_size / (BB * CC);   // 608 for pred_len = 96

    lr_forecast_skew4<<<GRID, NTH>>>(x, out, t_out_len);
}

// round 9
// speedup vs baseline: 1.1443x; 1.0055x over previous
#include <cuda_runtime.h>
#include <cstdint>

// Problem constants (fixed by the dataset instance).
#define BB 512
#define LL 512
#define CC 256
#define NTH 256
#define CSL 16                // channel slices per batch (16 ch = 4 float4 each)
#define C4S 4                 // float4 per slice
#define LGR 64                // l-groups (tid >> 2)
#define RITER (LL / LGR)      // 8 read iters per tile
#define TILES (BB * CSL)      // 8192
#define GRID 1024
#define TPB (TILES / GRID)    // 8 tiles per block
#define C4FULL (CC / 4)       // 64 float4 per full row
#define NWARP (NTH / 32)      // 8

// Least-squares constants for t = 0..511:
//   sum_t = 130816, sum_t2 = 44608256, denom = sum_t2 - sum_t^2/n = 11184768
#define SUM_T     130816.0f
#define K1        255.5f
#define INV_DENOM (1.0f / 11184768.0f)
#define INV_N     (1.0f / 512.0f)

__device__ __forceinline__ void f4add(float4& a, const float4 b) {
    a.x += b.x; a.y += b.y; a.z += b.z; a.w += b.w;
}

__device__ __forceinline__ void f4shfl_add(float4& a, int mask) {
    a.x += __shfl_xor_sync(0xffffffffu, a.x, mask);
    a.y += __shfl_xor_sync(0xffffffffu, a.y, mask);
    a.z += __shfl_xor_sync(0xffffffffu, a.z, mask);
    a.w += __shfl_xor_sync(0xffffffffu, a.w, mask);
}

__global__ __launch_bounds__(NTH)
void lr_forecast_skew8(const float* __restrict__ x,
                       float* __restrict__ out,
                       int t_out_len)
{
    const int g    = blockIdx.x;
    const int tid  = threadIdx.x;
    const int c4   = tid & (C4S - 1);  // 0..3
    const int lg   = tid >> 2;         // 0..63
    const int warp = tid >> 5;         // 0..7

    __shared__ float4 s_psy [NWARP][C4S];
    __shared__ float4 s_psty[NWARP][C4S];
    __shared__ float4 s_sl[C4S];
    __shared__ float4 s_ic[C4S];

    // ---- monolithic read phase (front-batched 8-deep LDG.128) ----
    auto read_tile = [&](int tile, float4& sl_o, float4& ic_o) {
        const int b  = tile >> 4;
        const int cs = tile & (CSL - 1);
        const float4* xb = reinterpret_cast<const float4*>(
                               x + (size_t)b * LL * CC) + cs * C4S + c4;
        float4 sy  = make_float4(0.f, 0.f, 0.f, 0.f);
        float4 sty = make_float4(0.f, 0.f, 0.f, 0.f);
        #pragma unroll
        for (int i = 0; i < RITER; i++) {       // 8 loads, fully unrolled
            int l = lg + i * LGR;
            float4 v = __ldg(&xb[(size_t)l * C4FULL]);
            float tf = (float)l;
            f4add(sy, v);
            sty.x = fmaf(tf, v.x, sty.x);
            sty.y = fmaf(tf, v.y, sty.y);
            sty.z = fmaf(tf, v.z, sty.z);
            sty.w = fmaf(tf, v.w, sty.w);
        }
        // warp-level reduce over the 8 lg values inside each warp
        // (lane = lg_local*4 + c4; xor masks 4,8,16 sum across lg_local)
        f4shfl_add(sy, 4);  f4shfl_add(sy, 8);  f4shfl_add(sy, 16);
        f4shfl_add(sty, 4); f4shfl_add(sty, 8); f4shfl_add(sty, 16);

        if ((tid & 31) < C4S) {        // lane 0..3 hold warp totals for c4 0..3
            s_psy [warp][tid & 3] = sy;
            s_psty[warp][tid & 3] = sty;
        }
        __syncthreads();

        if (tid < C4S) {
            float4 Sy = s_psy[0][tid], Sty = s_psty[0][tid];
            #pragma unroll
            for (int w = 1; w < NWARP; w++) {
                f4add(Sy,  s_psy [w][tid]);
                f4add(Sty, s_psty[w][tid]);
            }
            float4 SL, IC;
            SL.x = (Sty.x - K1 * Sy.x) * INV_DENOM;
            SL.y = (Sty.y - K1 * Sy.y) * INV_DENOM;
            SL.z = (Sty.z - K1 * Sy.z) * INV_DENOM;
            SL.w = (Sty.w - K1 * Sy.w) * INV_DENOM;
            IC.x = (Sy.x - SL.x * SUM_T) * INV_N;
            IC.y = (Sy.y - SL.y * SUM_T) * INV_N;
            IC.z = (Sy.z - SL.z * SUM_T) * INV_N;
            IC.w = (Sy.w - SL.w * SUM_T) * INV_N;
            s_sl[tid] = SL;
            s_ic[tid] = IC;
        }
        __syncthreads();
        sl_o = s_sl[c4];
        ic_o = s_ic[c4];
    };

    // ---- monolithic write phase ----
    auto write_tile = [&](int tile, float4 sl, float4 ic) {
        const int b  = tile >> 4;
        const int cs = tile & (CSL - 1);
        float4* ob = reinterpret_cast<float4*>(
                         out + (size_t)b * t_out_len * CC) + cs * C4S + c4;
        #pragma unroll 5
        for (int t = lg; t < t_out_len; t += LGR) {   // 9-10 iters
            float tf = (float)t;
            float4 o;
            o.x = fmaf(sl.x, tf, ic.x);
            o.y = fmaf(sl.y, tf, ic.y);
            o.z = fmaf(sl.z, tf, ic.z);
            o.w = fmaf(sl.w, tf, ic.w);
            ob[(size_t)t * C4FULL] = o;
        }
    };

    float4 sl0, ic0, sl1, ic1;

    if ((g & 1) == 0) {
        // Even blocks: R0 W0 R1 W1 ... R7 W7
        #pragma unroll
        for (int s = 0; s < TPB; s++) {
            int tile = g + s * GRID;
            read_tile(tile, sl0, ic0);
            write_tile(tile, sl0, ic0);
        }
    } else {
        // Odd blocks (depth-2 pipeline): R0 R1 W0 R2 W1 ... R7 W6 W7
        read_tile(g, sl0, ic0);
        #pragma unroll
        for (int s = 1; s < TPB; s++) {
            read_tile(g + s * GRID, sl1, ic1);
            write_tile(g + (s - 1) * GRID, sl0, ic0);
            sl0 = sl1; ic0 = ic1;
        }
        write_tile(g + (TPB - 1) * GRID, sl0, ic0);
    }
}

extern "C" void kernel_launch(void* const* d_in, const int* in_sizes, int n_in,
                              void* d_out, int out_size)
{
    const float* x = (const float*)d_in[0];
    float* out = (float*)d_out;
    int t_out_len = out_size / (BB * CC);   // 608 for pred_len = 96

    lr_forecast_skew8<<<GRID, NTH>>>(x, out, t_out_len);
}